// round 16
// baseline (speedup 1.0000x reference)
#include <cuda_runtime.h>
#include <cuda_bf16.h>
#include <cstdint>

// Problem constants (fixed shapes from reference)
#define T_STEPS 32768
#define D_IN    1024
#define U_HID   1024
#define NG      4096   // 4*U

#define N_LSTM_CTAS 128

// Producer tiles: 256 rows x 128 cols
#define GBM 256
#define GBN 128
#define GBK 16
#define ROW_GROUPS  128   // 32768 / 256
#define COL_TILES   32    // 4096 / 128
#define N_TILES     (ROW_GROUPS * COL_TILES)   // 4096

// Producer stays at most this many 256-row groups ahead of the consumer.
#define AHEAD_GROUPS 8u

// ---------------- static device scratch (no allocs allowed) ----------------
__device__ float              g_zx[(size_t)T_STEPS * NG];  // x@kernel + bias (row-major by t)
// packed hidden state: lo32 = h bits, hi32 = step tag. Double-buffered by parity.
__device__ unsigned long long g_hpk[2][U_HID];
__device__ unsigned           g_rowready[ROW_GROUPS];      // per-256-row-group counters
__device__ unsigned           g_progress;                  // consumer step / 256

// ============================================================================
// State init (runs every launch: graph replays reuse device globals)
// ============================================================================
__global__ void init_state() {
    const int i = threadIdx.x;
    if (i < U_HID) {
        g_hpk[0][i] = 0ull;                   // h=0, tag=0 -> step 0 matches instantly
        g_hpk[1][i] = 0x8000000000000000ull;  // tag never matches a real step
    }
    if (i < ROW_GROUPS) g_rowready[i] = 0u;
    if (i == 0) g_progress = 0u;
}

// ============================================================================
// MEGA-KERNEL: CTAs 0..127 = persistent LSTM recurrence (EXACT R10 proven
// form — untouched); CTAs 128.. = throttled GEMM producers (8x4 microtile on
// 256x128 tiles, ~2x R9 rate when active, paced just-in-time so their
// instantaneous L2 traffic never exceeds R9's spread-out average).
// ============================================================================
__global__ __launch_bounds__(1024, 1) void mega(
    const float* __restrict__ x,     // [T, D]
    const float* __restrict__ kw,    // [D, 4U]
    const float* __restrict__ bias,  // [4U]
    const float* __restrict__ Rw,    // [U, 4U]
    float* __restrict__ out,         // [T, U]
    int nGemm)
{
    // ---- shared memory (union by role: each CTA touches only its own set) ----
    __shared__ float As[GBK][GBM + 4];            // 16 x 260 floats
    __shared__ __align__(16) float Bs[GBK][GBN];  // 8 KB
    __shared__ __align__(16) float sh_h[U_HID];
    __shared__ float sp[2][32 * 33];
    __shared__ float zs[32];

    const int tid = threadIdx.x;

    // ========================== GEMM producer role ==========================
    if (blockIdx.x >= N_LSTM_CTAS) {
        const int rank = blockIdx.x - N_LSTM_CTAS;

        // loaders: A 256x16 (one float4 along k per thread), B 16x128
        const int aRow = tid >> 2;          // 0..255
        const int ac4  = (tid & 3) * 4;     // 0,4,8,12
        const int bRow = tid >> 6;          // 0..15
        const int bc2  = (tid & 63) * 2;    // 0,2,..,126
        // compute mapping: 8 rows x 4 cols per thread
        const int tx   = tid & 31;          // cols tx*4 .. tx*4+3
        const int ty   = tid >> 5;          // rows ty*8 .. ty*8+7

        for (int tt = rank; tt < N_TILES; tt += nGemm) {
            const int rowT = tt >> 5;       // row-group-major => ready ascending
            const int colT = tt & 31;

            // Throttle: stay <= AHEAD_GROUPS groups ahead of the consumer.
            if ((unsigned)rowT > AHEAD_GROUPS) {
                if (tid == 0) {
                    for (;;) {
                        unsigned p;
                        asm volatile("ld.relaxed.gpu.global.u32 %0, [%1];"
                                     : "=r"(p) : "l"(&g_progress));
                        if ((unsigned)rowT <= p + AHEAD_GROUPS) break;
                        __nanosleep(4000);
                    }
                }
                __syncthreads();
            }

            const int cRow = rowT * GBM;
            const int cCol = colT * GBN;
            const float* Ap = x  + (size_t)cRow * D_IN;
            const float* Bp = kw + cCol;

            float acc[8][4];
#pragma unroll
            for (int i = 0; i < 8; ++i)
#pragma unroll
                for (int j = 0; j < 4; ++j) acc[i][j] = 0.f;

            for (int kt = 0; kt < D_IN / GBK; ++kt) {
                // global loads (overlap: other warps still in prev FMA loop)
                float4 ra = *(const float4*)&Ap[(size_t)aRow * D_IN + kt * GBK + ac4];
                float2 rb = *(const float2*)&Bp[(size_t)(kt * GBK + bRow) * NG + bc2];
                __syncthreads();   // previous iteration's smem reads complete
                As[ac4 + 0][aRow] = ra.x;
                As[ac4 + 1][aRow] = ra.y;
                As[ac4 + 2][aRow] = ra.z;
                As[ac4 + 3][aRow] = ra.w;
                *(float2*)&Bs[bRow][bc2] = rb;
                __syncthreads();   // tile staged

#pragma unroll
                for (int k = 0; k < GBK; ++k) {
                    // A: 8 rows = 2 float4, warp-broadcast (all lanes same ty)
                    float4 a0 = *(const float4*)&As[k][ty * 8];
                    float4 a1 = *(const float4*)&As[k][ty * 8 + 4];
                    float4 bv = *(const float4*)&Bs[k][tx * 4];
                    float ar[8] = {a0.x, a0.y, a0.z, a0.w, a1.x, a1.y, a1.z, a1.w};
                    float br[4] = {bv.x, bv.y, bv.z, bv.w};
#pragma unroll
                    for (int i = 0; i < 8; ++i)
#pragma unroll
                        for (int j = 0; j < 4; ++j)
                            acc[i][j] = fmaf(ar[i], br[j], acc[i][j]);
                }
            }

            // epilogue: + bias, 8 coalesced float4 row-stores
            float4 bb4 = *(const float4*)&bias[cCol + tx * 4];
#pragma unroll
            for (int i = 0; i < 8; ++i) {
                const int r = cRow + ty * 8 + i;
                float4 o = make_float4(acc[i][0] + bb4.x, acc[i][1] + bb4.y,
                                       acc[i][2] + bb4.z, acc[i][3] + bb4.w);
                *(float4*)&g_zx[(size_t)r * NG + cCol + tx * 4] = o;
            }
            __syncthreads();          // all stores of this tile issued
            if (tid == 0) {
                __threadfence();      // gpu-scope: make tile stores visible
                asm volatile("red.release.gpu.global.add.u32 [%0], %1;"
                             :: "l"(&g_rowready[rowT]), "r"(1u) : "memory");
            }
            __syncthreads();
        }
        return;
    }

    // ========================== LSTM recurrence role ==========================
    const int w   = tid >> 5;
    const int l   = tid & 31;
    const int u0  = blockIdx.x * 8;
    // stage-1 column for lane l; stage-2 column for warp w
    const int col  = ((l >> 3) << 10) + u0 + (l & 7);
    const int col2 = ((w >> 3) << 10) + u0 + (w & 7);

    // packed weight pairs: W2[m] = {R[32w+2m][col], R[32w+2m+1][col]}
    unsigned long long W2[16];
    {
        const float* wp = Rw + ((size_t)(w << 5)) * NG + col;
#pragma unroll
        for (int m = 0; m < 16; ++m) {
            float w0 = wp[(size_t)(2 * m) * NG];
            float w1 = wp[(size_t)(2 * m + 1) * NG];
            asm("mov.b64 %0, {%1, %2};" : "=l"(W2[m]) : "f"(w0), "f"(w1));
        }
    }

    float cst = 0.f;                       // cell state (warp 0, lanes 0..7)
    const float* zxp = g_zx + col2;

    // zx readiness tracking (only l==0 lanes use it); 256 steps per group
    int zreadyT = 0;
    auto wait_tile = [&](int grp) {
        unsigned v;
        do {
            asm volatile("ld.acquire.gpu.global.u32 %0, [%1];"
                         : "=r"(v) : "l"(&g_rowready[grp]) : "memory");
        } while (v < (unsigned)COL_TILES);
    };

    float zxv = 0.f;
    if (l == 0) {               // initial zx (row 0) — wait for group 0
        wait_tile(0);
        zreadyT = 1;
        zxv = __ldg(zxp);
    }

    const int e  = (w << 5) + l;           // element this lane polls
    const int jj = l & 7;

    for (int t = 0; t < T_STEPS; ++t) {
        // prefetch next step's zx early (gated by group readiness)
        float zxn = 0.f;
        if (l == 0 && t + 1 < T_STEPS) {
            const int tl = (t + 1) >> 8;
            if (tl >= zreadyT) { wait_tile(tl); zreadyT = tl + 1; }
            zxn = __ldg(&zxp[(size_t)(t + 1) * NG]);
        }

        // poll the packed {h, tag} word; tag==t => h is the step-t value
        {
            const unsigned long long* src = &g_hpk[t & 1][e];
            unsigned long long pk;
            do {
                asm volatile("ld.volatile.global.u64 %0, [%1];"
                             : "=l"(pk) : "l"(src));
            } while ((unsigned)(pk >> 32) != (unsigned)t);
            sh_h[e] = __uint_as_float((unsigned)pk);
        }
        __syncwarp();

        float* const spb = sp[t & 1];      // step-parity buffer

        // stage 1: packed-f32x2 partial dot over rows [32w,32w+32) for `col`
        unsigned long long acc0 = 0ull, acc1 = 0ull;
        const ulonglong2* h2 = reinterpret_cast<const ulonglong2*>(sh_h + (w << 5));
#pragma unroll
        for (int k = 0; k < 8; ++k) {
            ulonglong2 hv = h2[k];  // all lanes same address -> smem broadcast
            asm("fma.rn.f32x2 %0, %1, %2, %3;"
                : "=l"(acc0) : "l"(hv.x), "l"(W2[2 * k]),     "l"(acc0));
            asm("fma.rn.f32x2 %0, %1, %2, %3;"
                : "=l"(acc1) : "l"(hv.y), "l"(W2[2 * k + 1]), "l"(acc1));
        }
        float a0, a1, b0, b1;
        asm("mov.b64 {%0, %1}, %2;" : "=f"(a0), "=f"(a1) : "l"(acc0));
        asm("mov.b64 {%0, %1}, %2;" : "=f"(b0), "=f"(b1) : "l"(acc1));
        spb[l * 33 + w] = (a0 + b0) + (a1 + b1);
        __syncthreads();  // bar A: all partials in sp

        // stage 2: warp w reduces its column; 4 partials/lane then 3 shfls;
        // lane 0 applies the activation (parallel across warps)
        {
            const float* spc = spb + w * 33 + jj;
            float s = (spc[0] + spc[8]) + (spc[16] + spc[24]);
            s += __shfl_xor_sync(0xffffffffu, s, 4);
            s += __shfl_xor_sync(0xffffffffu, s, 2);
            s += __shfl_xor_sync(0xffffffffu, s, 1);
            if (l == 0) {
                const float z = s + zxv;
                const int   q = w >> 3;
                if (q == 2) {               // g gate: tanh
                    const float zc = fminf(fmaxf(z, -15.f), 15.f);
                    const float ee = __expf(2.f * zc);
                    zs[w] = __fdividef(ee - 1.f, ee + 1.f);
                } else {                    // i,f,o gates: sigmoid
                    const float ee = __expf(-z);
                    zs[w] = __fdividef(1.f, 1.f + ee);
                }
            }
        }
        __syncthreads();  // bar B: activated gate values ready

        // consumer progress beacon for producer throttle (off critical path:
        // warp 16 is idle in the gate phase; one 4B store every 256 steps)
        if (blockIdx.x == 0 && w == 16 && l == 0 && (t & 255) == 255) {
            asm volatile("st.relaxed.gpu.global.u32 [%0], %1;"
                         :: "l"(&g_progress), "r"((unsigned)(t >> 8)) : "memory");
        }

        // final: warp 0, lanes 0..7 update cell and publish
        if (w == 0 && l < 8) {
            const float ig = zs[l],      fg = zs[8 + l];
            const float gg = zs[16 + l], og = zs[24 + l];
            const float c2 = fg * cst + ig * gg;
            cst = c2;
            const float cc = fminf(fmaxf(c2, -15.f), 15.f);
            const float ec = __expf(2.f * cc);
            const float h  = og * __fdividef(ec - 1.f, ec + 1.f);
            // publish FIRST: one coalesced 64B wavefront (8 lanes x 8B)
            unsigned long long pkw;
            asm("mov.b64 %0, {%1, %2};"
                : "=l"(pkw) : "f"(h), "r"((unsigned)(t + 1)));
            asm volatile("st.volatile.global.u64 [%0], %1;"
                         :: "l"(&g_hpk[(t + 1) & 1][u0 + l]), "l"(pkw)
                         : "memory");
            out[(size_t)t * U_HID + u0 + l] = h;    // off critical path
        }
        zxv = zxn;
        // no trailing barrier: zs(t+1) writes happen after bar A(t+1), which
        // warp 0 only reaches after gates; sp reuse is parity-buffered.
    }
}

// ============================================================================
extern "C" void kernel_launch(void* const* d_in, const int* in_sizes, int n_in,
                              void* d_out, int out_size) {
    const float* x    = (const float*)d_in[0];  // [1, 32768, 1024]
    const float* kw   = (const float*)d_in[1];  // [1024, 4096]
    const float* rw   = (const float*)d_in[2];  // [1024, 4096]
    const float* bias = (const float*)d_in[3];  // [4096]
    float* out = (float*)d_out;                 // [1, 32768, 1024]

    int sms = 148;
    cudaDeviceGetAttribute(&sms, cudaDevAttrMultiProcessorCount, 0);
    int nGemm = sms - N_LSTM_CTAS;              // producer CTAs on spare SMs
    if (nGemm < 1) nGemm = 1;

    init_state<<<1, 1024>>>();
    mega<<<N_LSTM_CTAS + nGemm, 1024>>>(x, kw, bias, rw, out, nGemm);
}

// round 17
// speedup vs baseline: 1.1395x; 1.1395x over previous
#include <cuda_runtime.h>
#include <cuda_bf16.h>
#include <cstdint>

// Problem constants (fixed shapes from reference)
#define T_STEPS 32768
#define D_IN    1024
#define U_HID   1024
#define NG      4096   // 4*U

#define N_LSTM_CTAS 128

// Producer tiles: 256 rows x 128 cols
#define GBM 256
#define GBN 128
#define GBK 16
#define ROW_GROUPS  128   // 32768 / 256
#define COL_TILES   32    // 4096 / 128
#define N_TILES     (ROW_GROUPS * COL_TILES)   // 4096

// ---------------- static device scratch (no allocs allowed) ----------------
__device__ float              g_zx[(size_t)T_STEPS * NG];  // x@kernel + bias (row-major by t)
// packed hidden state: lo32 = h bits, hi32 = step tag. Double-buffered by parity.
__device__ unsigned long long g_hpk[2][U_HID];
__device__ unsigned           g_rowready[ROW_GROUPS];      // per-256-row-group counters

// ============================================================================
// State init (runs every launch: graph replays reuse device globals)
// ============================================================================
__global__ void init_state() {
    const int i = threadIdx.x;
    if (i < U_HID) {
        g_hpk[0][i] = 0ull;                   // h=0, tag=0 -> step 0 matches instantly
        g_hpk[1][i] = 0x8000000000000000ull;  // tag never matches a real step
    }
    if (i < ROW_GROUPS) g_rowready[i] = 0u;
}

// ============================================================================
// MEGA-KERNEL: CTAs 0..127 = persistent LSTM recurrence with a fused warp-0
// tail (single barrier per step); CTAs 128.. = GEMM producers (8x4 microtile
// on 256x128 tiles, unthrottled — proven neutral to throttle).
// ============================================================================
__global__ __launch_bounds__(1024, 1) void mega(
    const float* __restrict__ x,     // [T, D]
    const float* __restrict__ kw,    // [D, 4U]
    const float* __restrict__ bias,  // [4U]
    const float* __restrict__ Rw,    // [U, 4U]
    float* __restrict__ out,         // [T, U]
    int nGemm)
{
    // ---- shared memory (union by role: each CTA touches only its own set) ----
    __shared__ float As[GBK][GBM + 4];            // producers
    __shared__ __align__(16) float Bs[GBK][GBN];  // producers
    __shared__ __align__(16) float sh_h[U_HID];   // recurrence
    __shared__ float sp[2][32 * 33];              // recurrence

    const int tid = threadIdx.x;

    // ========================== GEMM producer role ==========================
    if (blockIdx.x >= N_LSTM_CTAS) {
        const int rank = blockIdx.x - N_LSTM_CTAS;

        // loaders: A 256x16 (one float4 along k per thread), B 16x128
        const int aRow = tid >> 2;          // 0..255
        const int ac4  = (tid & 3) * 4;     // 0,4,8,12
        const int bRow = tid >> 6;          // 0..15
        const int bc2  = (tid & 63) * 2;    // 0,2,..,126
        // compute mapping: 8 rows x 4 cols per thread
        const int tx   = tid & 31;          // cols tx*4 .. tx*4+3
        const int ty   = tid >> 5;          // rows ty*8 .. ty*8+7

        for (int tt = rank; tt < N_TILES; tt += nGemm) {
            const int rowT = tt >> 5;       // row-group-major => ready ascending
            const int colT = tt & 31;
            const int cRow = rowT * GBM;
            const int cCol = colT * GBN;
            const float* Ap = x  + (size_t)cRow * D_IN;
            const float* Bp = kw + cCol;

            float acc[8][4];
#pragma unroll
            for (int i = 0; i < 8; ++i)
#pragma unroll
                for (int j = 0; j < 4; ++j) acc[i][j] = 0.f;

            for (int kt = 0; kt < D_IN / GBK; ++kt) {
                float4 ra = *(const float4*)&Ap[(size_t)aRow * D_IN + kt * GBK + ac4];
                float2 rb = *(const float2*)&Bp[(size_t)(kt * GBK + bRow) * NG + bc2];
                __syncthreads();   // previous iteration's smem reads complete
                As[ac4 + 0][aRow] = ra.x;
                As[ac4 + 1][aRow] = ra.y;
                As[ac4 + 2][aRow] = ra.z;
                As[ac4 + 3][aRow] = ra.w;
                *(float2*)&Bs[bRow][bc2] = rb;
                __syncthreads();   // tile staged

#pragma unroll
                for (int k = 0; k < GBK; ++k) {
                    float4 a0 = *(const float4*)&As[k][ty * 8];
                    float4 a1 = *(const float4*)&As[k][ty * 8 + 4];
                    float4 bv = *(const float4*)&Bs[k][tx * 4];
                    float ar[8] = {a0.x, a0.y, a0.z, a0.w, a1.x, a1.y, a1.z, a1.w};
                    float br[4] = {bv.x, bv.y, bv.z, bv.w};
#pragma unroll
                    for (int i = 0; i < 8; ++i)
#pragma unroll
                        for (int j = 0; j < 4; ++j)
                            acc[i][j] = fmaf(ar[i], br[j], acc[i][j]);
                }
            }

            float4 bb4 = *(const float4*)&bias[cCol + tx * 4];
#pragma unroll
            for (int i = 0; i < 8; ++i) {
                const int r = cRow + ty * 8 + i;
                float4 o = make_float4(acc[i][0] + bb4.x, acc[i][1] + bb4.y,
                                       acc[i][2] + bb4.z, acc[i][3] + bb4.w);
                *(float4*)&g_zx[(size_t)r * NG + cCol + tx * 4] = o;
            }
            __syncthreads();          // all stores of this tile issued
            if (tid == 0) {
                __threadfence();      // gpu-scope: make tile stores visible
                asm volatile("red.release.gpu.global.add.u32 [%0], %1;"
                             :: "l"(&g_rowready[rowT]), "r"(1u) : "memory");
            }
            __syncthreads();
        }
        return;
    }

    // ========================== LSTM recurrence role ==========================
    const int w   = tid >> 5;
    const int l   = tid & 31;
    const int u0  = blockIdx.x * 8;
    // stage-1 column for lane l (CTA column l = 8q+u => global gate column)
    const int col = ((l >> 3) << 10) + u0 + (l & 7);

    // packed weight pairs: W2[m] = {R[32w+2m][col], R[32w+2m+1][col]}
    unsigned long long W2[16];
    {
        const float* wp = Rw + ((size_t)(w << 5)) * NG + col;
#pragma unroll
        for (int m = 0; m < 16; ++m) {
            float w0 = wp[(size_t)(2 * m) * NG];
            float w1 = wp[(size_t)(2 * m + 1) * NG];
            asm("mov.b64 %0, {%1, %2};" : "=l"(W2[m]) : "f"(w0), "f"(w1));
        }
    }

    float cst = 0.f;                     // cell state (warp 0, lanes 0..7)
    // zx pointer for warp 0, lane l: column `col`, walk rows (coalesced 4x32B)
    const float* zxp = g_zx + col;

    // zx readiness tracking (warp 0 only); 256 steps per group
    int zreadyT = 0;
    auto wait_tile = [&](int grp) {
        unsigned v;
        do {
            asm volatile("ld.acquire.gpu.global.u32 %0, [%1];"
                         : "=r"(v) : "l"(&g_rowready[grp]) : "memory");
        } while (v < (unsigned)COL_TILES);
    };

    float zxv = 0.f;
    if (w == 0) {               // initial zx (row 0) — wait for group 0
        wait_tile(0);
        zreadyT = 1;
        zxv = __ldg(zxp);
    }

    const int e = (w << 5) + l;          // element this lane polls
    const int q = l >> 3;                // gate index of this lane's column

    for (int t = 0; t < T_STEPS; ++t) {
        // warp 0: prefetch next step's zx early (gated by group readiness)
        float zxn = 0.f;
        if (w == 0 && t + 1 < T_STEPS) {
            const int tl = (t + 1) >> 8;
            if (tl >= zreadyT) { wait_tile(tl); zreadyT = tl + 1; }
            zxn = __ldg(&zxp[(size_t)(t + 1) * NG]);
        }

        // poll the packed {h, tag} word; tag==t => h is the step-t value
        {
            const unsigned long long* src = &g_hpk[t & 1][e];
            unsigned long long pk;
            do {
                asm volatile("ld.volatile.global.u64 %0, [%1];"
                             : "=l"(pk) : "l"(src));
            } while ((unsigned)(pk >> 32) != (unsigned)t);
            sh_h[e] = __uint_as_float((unsigned)pk);
        }
        __syncwarp();

        float* const spb = sp[t & 1];      // step-parity buffer

        // stage 1: packed-f32x2 partial dot over rows [32w,32w+32) for `col`
        unsigned long long acc0 = 0ull, acc1 = 0ull;
        const ulonglong2* h2 = reinterpret_cast<const ulonglong2*>(sh_h + (w << 5));
#pragma unroll
        for (int k = 0; k < 8; ++k) {
            ulonglong2 hv = h2[k];  // all lanes same address -> smem broadcast
            asm("fma.rn.f32x2 %0, %1, %2, %3;"
                : "=l"(acc0) : "l"(hv.x), "l"(W2[2 * k]),     "l"(acc0));
            asm("fma.rn.f32x2 %0, %1, %2, %3;"
                : "=l"(acc1) : "l"(hv.y), "l"(W2[2 * k + 1]), "l"(acc1));
        }
        float a0, a1, b0, b1;
        asm("mov.b64 {%0, %1}, %2;" : "=f"(a0), "=f"(a1) : "l"(acc0));
        asm("mov.b64 {%0, %1}, %2;" : "=f"(b0), "=f"(b1) : "l"(acc1));
        spb[l * 33 + w] = (a0 + b0) + (a1 + b1);
        __syncthreads();  // bar A: all partials in sp (the ONLY barrier)

        // fused stage2 + gates: warp 0 only. Lane l reduces column l
        // (bank (l+k)&31: conflict-free), applies its activation, then 3
        // bfly shfls deliver f,g,o to lanes 0..7 which update c and publish.
        if (w == 0) {
            const float* spc = spb + l * 33;
            float s0 = 0.f, s1 = 0.f, s2 = 0.f, s3 = 0.f;
#pragma unroll
            for (int k = 0; k < 32; k += 4) {
                s0 += spc[k];
                s1 += spc[k + 1];
                s2 += spc[k + 2];
                s3 += spc[k + 3];
            }
            const float z = (s0 + s1) + (s2 + s3) + zxv;
            // unified activation: q==2 -> tanh(z), else sigmoid(z)
            //   tanh(z)   = (1 - e^{-2z}) / (1 + e^{-2z})
            //   sigmoid(z)=  1            / (1 + e^{-z})
            const bool  tg = (q == 2);
            float a = tg ? (2.f * z) : z;
            a = fminf(fmaxf(a, -80.f), 80.f);
            const float ee  = __expf(-a);
            const float num = tg ? (1.f - ee) : 1.f;
            const float act = __fdividef(num, 1.f + ee);
            // gather f, g, o to lanes 0..7
            const float vf = __shfl_xor_sync(0xffffffffu, act, 8);
            const float vg = __shfl_xor_sync(0xffffffffu, act, 16);
            const float vo = __shfl_xor_sync(0xffffffffu, act, 24);
            if (l < 8) {
                const float c2 = vf * cst + act * vg;   // act = i on lanes 0..7
                cst = c2;
                const float cc = fminf(fmaxf(2.f * c2, -80.f), 80.f);
                const float ec = __expf(-cc);
                const float h  = vo * __fdividef(1.f - ec, 1.f + ec);
                // publish FIRST: one coalesced 64B wavefront (8 lanes x 8B)
                unsigned long long pkw;
                asm("mov.b64 %0, {%1, %2};"
                    : "=l"(pkw) : "f"(h), "r"((unsigned)(t + 1)));
                asm volatile("st.volatile.global.u64 [%0], %1;"
                             :: "l"(&g_hpk[(t + 1) & 1][u0 + l]), "l"(pkw)
                             : "memory");
                out[(size_t)t * U_HID + u0 + l] = h;    // off critical path
            }
        }
        zxv = zxn;
        // no trailing barrier: warps 1..31 go straight to the next poll; sp
        // reuse is parity-buffered, and bar A(t+1) fences warp 0's reads.
    }
}

// ============================================================================
extern "C" void kernel_launch(void* const* d_in, const int* in_sizes, int n_in,
                              void* d_out, int out_size) {
    const float* x    = (const float*)d_in[0];  // [1, 32768, 1024]
    const float* kw   = (const float*)d_in[1];  // [1024, 4096]
    const float* rw   = (const float*)d_in[2];  // [1024, 4096]
    const float* bias = (const float*)d_in[3];  // [4096]
    float* out = (float*)d_out;                 // [1, 32768, 1024]

    int sms = 148;
    cudaDeviceGetAttribute(&sms, cudaDevAttrMultiProcessorCount, 0);
    int nGemm = sms - N_LSTM_CTAS;              // producer CTAs on spare SMs
    if (nGemm < 1) nGemm = 1;

    init_state<<<1, 1024>>>();
    mega<<<N_LSTM_CTAS + nGemm, 1024>>>(x, kw, bias, rw, out, nGemm);
}